// round 16
// baseline (speedup 1.0000x reference)
#include <cuda_runtime.h>

typedef unsigned long long ull;

// ---------------- problem dimensions ----------------
static constexpr int D1=41, H1=200, W1=176; static constexpr int N1=D1*H1*W1;   // 1,443,200
static constexpr int D2=21, H2=100, W2=88;  static constexpr int N2=D2*H2*W2;   // 184,800
static constexpr int D3=11, H3=50,  W3=44;  static constexpr int N3=D3*H3*W3;   // 24,200
static constexpr int D4=5,  H4=25,  W4=22;  static constexpr int N4=D4*H4*W4;   // 2,750
static constexpr int D5=2,  H5=25,  W5=22;  static constexpr int N5=D5*H5*W5;   // 1,100

// ---------------- static device scratch ----------------
__device__ __align__(16) float g_bufA[16 * N1];   // 92.4 MB ping
__device__ __align__(16) float g_bufB[16 * N1];   // 92.4 MB pong
__device__ float g_mask2[N2];
__device__ float g_mask3[N3];
__device__ float g_mask4[N4];
__device__ float g_mask5[N5];
__device__ __align__(16) float g_wr[710592];      // reordered weights, all 12 layers
__device__ int   g_list[N1];
__device__ int   g_cnt;

// weight region metadata (floats)
__device__ __constant__ int c_off[12] = {0, 1728, 8640, 22464, 50112, 77760, 133056,
                                         243648, 354240, 464832, 575424, 686016};
__device__ __constant__ int c_CI[12] = {4, 16, 16, 32, 32, 32, 64, 64, 64, 64, 64, 64};
__device__ __constant__ int c_CO[12] = {16, 16, 32, 32, 32, 64, 64, 64, 64, 64, 64, 128};
__device__ __constant__ int c_K3[12] = {27, 27, 27, 27, 27, 27, 27, 27, 27, 27, 27, 3};

struct WPtrs { const float* w[12]; };

// ---------------- f32x2 + cp.async helpers ----------------
__device__ __forceinline__ void f2_unpack(ull v, float& lo, float& hi) {
    asm("mov.b64 {%0, %1}, %2;" : "=f"(lo), "=f"(hi) : "l"(v));
}
#define FMA_F32X2(d, a, b, c) \
    asm("fma.rn.f32x2 %0, %1, %2, %3;" : "=l"(d) : "l"(a), "l"(b), "l"(c))

__device__ __forceinline__ void cp4(float* dst, const float* src) {
    unsigned d = (unsigned)__cvta_generic_to_shared(dst);
    asm volatile("cp.async.ca.shared.global [%0], [%1], 4;" :: "r"(d), "l"(src));
}
#define CP_COMMIT() asm volatile("cp.async.commit_group;" ::: "memory")
#define CP_WAIT1()  asm volatile("cp.async.wait_group 1;"  ::: "memory")

// ---------------- mask box probe (early exit) ----------------
__device__ __forceinline__ float probe_box(const float* __restrict__ mask,
                                           int z0, int z1, int y0, int y1,
                                           int x0, int x1) {
    z0 = max(z0, 0); y0 = max(y0, 0); x0 = max(x0, 0);
    z1 = min(z1, D1 - 1); y1 = min(y1, H1 - 1); x1 = min(x1, W1 - 1);
    for (int z = z0; z <= z1; z++)
        for (int y = y0; y <= y1; y++)
            for (int x = x0; x <= x1; x++)
                if (__ldg(mask + (z * H1 + y) * W1 + x) != 0.0f) return 1.0f;
    return 0.0f;
}

// ---------------- mega prelude: weights + zero bufB + compact + all masks ----------------
__global__ void prelude_kernel(WPtrs p, const float* __restrict__ mask,
                               float* __restrict__ wr, float4* __restrict__ zb,
                               float* __restrict__ m2o, float* __restrict__ m3o,
                               float* __restrict__ m4o, float* __restrict__ m5o) {
    int t  = blockIdx.x * blockDim.x + threadIdx.x;
    int nt = gridDim.x * blockDim.x;

    const int NZ4 = (16 * N1) / 4;
    for (int i = t; i < NZ4; i += nt)
        zb[i] = make_float4(0.f, 0.f, 0.f, 0.f);

    if (t < N1 && mask[t] != 0.0f) {
        int q = atomicAdd(&g_cnt, 1);
        g_list[q] = t;
    }

    if (t < 710592) {
        int L = 0, base = 0;
        #pragma unroll
        for (int i = 0; i < 12; i++) {
            int n = c_CO[i] * c_CI[i] * c_K3[i];
            if (t >= base && t < base + n) { L = i; }
            base += n;
        }
        base = c_off[L];
        int local = t - base;
        int K3 = c_K3[L], CI = c_CI[L], CO = c_CO[L];
        int k  = local % K3;
        int r  = local / K3;
        int ci = r % CI;
        int co = r / CI;
        wr[base + (ci * K3 + k) * CO + co] = p.w[L][local];
    }

    if (t < N2) {
        int x = t % W2; int r = t / W2; int y = r % H2; int z = r / H2;
        m2o[t] = probe_box(mask, 2*z-1, 2*z+1, 2*y-1, 2*y+1, 2*x-1, 2*x+1);
    }
    if (t < N3) {
        int x = t % W3; int r = t / W3; int y = r % H3; int z = r / H3;
        m3o[t] = probe_box(mask, 4*z-3, 4*z+3, 4*y-3, 4*y+3, 4*x-3, 4*x+3);
    }
    if (t < N4) {
        int x = t % W4; int r = t / W4; int y = r % H4; int z = r / H4;
        m4o[t] = probe_box(mask, 8*z-3, 8*z+11, 8*y-7, 8*y+7, 8*x-7, 8*x+7);
    }
    if (t < N5) {
        int x = t % W5; int r = t / W5; int y = r % H5; int z = r / H5;
        m5o[t] = probe_box(mask, 16*z-3, 16*z+27, 8*y-7, 8*y+7, 8*x-7, 8*x+7);
    }
}

// ---------------- sparse gather subm conv with TAP SKIP (3x3x3, s1, p1) ----------------
template<int CI, int CO>
__global__ void subm_gather_kernel(const float* __restrict__ in, const float* __restrict__ mask,
                                   const float* __restrict__ wr, const float* __restrict__ bn,
                                   float* __restrict__ out, int D, int H, int W) {
    const int q = threadIdx.x;       // [0, CO/4)
    const int n = g_cnt;
    const int DHW = D * H * W;
    for (int e = blockIdx.x * blockDim.y + threadIdx.y; e < n; e += gridDim.x * blockDim.y) {
        const int idx = g_list[e];
        const int x  = idx % W;
        const int zy = idx / W;
        const int y  = zy % H;
        const int z  = zy / H;

        float acc[4] = {0.f, 0.f, 0.f, 0.f};
        #pragma unroll
        for (int kz = 0; kz < 3; kz++) {
            int zi = z - 1 + kz; if ((unsigned)zi >= (unsigned)D) continue;
            #pragma unroll
            for (int ky = 0; ky < 3; ky++) {
                int yi = y - 1 + ky; if ((unsigned)yi >= (unsigned)H) continue;
                const int rowb = (zi * H + yi) * W + x;
                #pragma unroll
                for (int kx = 0; kx < 3; kx++) {
                    int xi = x - 1 + kx;
                    if ((unsigned)xi >= (unsigned)W) continue;
                    if (__ldg(mask + rowb + kx - 1) == 0.0f) continue;   // tap skip
                    const float* __restrict__ ptap = in + rowb + kx - 1;
                    const float* __restrict__ wtap =
                        wr + ((kz * 3 + ky) * 3 + kx) * CO + 4 * q;
                    #pragma unroll
                    for (int ci = 0; ci < CI; ci++) {
                        float iv = __ldg(ptap + ci * DHW);
                        float4 w4 = *reinterpret_cast<const float4*>(wtap + ci * 27 * CO);
                        acc[0] += iv * w4.x;
                        acc[1] += iv * w4.y;
                        acc[2] += iv * w4.z;
                        acc[3] += iv * w4.w;
                    }
                }
            }
        }
        #pragma unroll
        for (int j = 0; j < 4; j++) {
            int co = 4 * q + j;
            float g  = bn[co];
            float b  = bn[CO + co];
            float mu = bn[2 * CO + co];
            float vr = bn[3 * CO + co];
            float sc = g * rsqrtf(vr + 1e-3f);
            float sh = b - mu * sc;
            float val = fmaxf(acc[j] * sc + sh, 0.0f);
            out[((co * D + z) * (long)H + y) * W + x] = val;
        }
    }
}

// ---------------- dense conv: cp.async pipeline + DUPLICATED-SMEM f32x2 ----------------
// Each staged input value is stored TWICE in adjacent smem slots, so one aligned
// LDS.64 yields a ready (v,v) f32x2 operand — no register duplication MOVs.
// block = (CO/4, OWT/V, YB).
template<int CI, int CO, int CIPS, int V, int YB, int OWT, int NT,
         int KD, int KH, int KW, int SD, int SH, int SW, int PD, int PH, int PW>
__global__ void __launch_bounds__(NT, 2)
conv_smem_kernel(const float* __restrict__ in, const float* __restrict__ wr,
                 const float* __restrict__ bn, const float* __restrict__ omask,
                 float* __restrict__ out,
                 int ID, int IH, int IW, int OD, int OH, int OW) {
    constexpr int NSEG    = (V - 1) * SW + KW;
    constexpr int SMH     = (YB - 1) * SH + KH;
    constexpr int SMW_E   = (OWT - 1) * SW + KW;          // elements per row
    constexpr int SMW2    = 2 * SMW_E;                    // duplicated row width
    constexpr int SMTOT_E = KD * SMH * SMW_E;             // elements per CI slice
    constexpr int SMTOT   = KD * SMH * SMW2;              // floats per CI slice (dup)
    constexpr int NLOAD   = (SMTOT_E + NT - 1) / NT;
    constexpr int NS      = CI / CIPS;

    __shared__ __align__(16) float sm[2][CIPS * SMTOT];

    const int q   = threadIdx.x;
    const int tz  = threadIdx.z;
    const int x0  = threadIdx.y * V;
    const int y   = blockIdx.y * YB + tz;
    const int z   = blockIdx.z;
    const int tid = threadIdx.x + blockDim.x * (threadIdx.y + blockDim.y * threadIdx.z);

    const bool active = (y < OH);
    const int CIstride = ID * IH * IW;

    for (int i = tid; i < 2 * CIPS * SMTOT; i += NT)
        (&sm[0][0])[i] = 0.0f;

    // per-thread loader tuples over ELEMENT index (CI-invariant)
    const int zi_base = z * SD - PD;
    const int yi_base = blockIdx.y * YB * SH - PH;
    int goff[NLOAD];
    unsigned vm = 0;
    #pragma unroll
    for (int j = 0; j < NLOAD; j++) {
        int i  = tid + j * NT;
        int s  = i % SMW_E;
        int t2 = i / SMW_E;
        int r  = t2 % SMH;
        int kz = t2 / SMH;
        int zi = zi_base + kz;
        int yi = yi_base + r;
        int xi = s - PW;
        bool ok = (i < SMTOT_E) && ((unsigned)zi < (unsigned)ID) &&
                  ((unsigned)yi < (unsigned)IH) && ((unsigned)xi < (unsigned)IW);
        goff[j] = ok ? ((zi * IH + yi) * IW + xi) : 0;
        if (ok) vm |= (1u << j);
    }
    __syncthreads();

    float m[V];
    float msum = 0.0f;
    if (active) {
        const int obase = (z * OH + y) * OW;
        #pragma unroll
        for (int v = 0; v < V; v++) {
            m[v] = (x0 + v < OW) ? omask[obase + x0 + v] : 0.0f;
            msum += m[v];
        }
    } else {
        #pragma unroll
        for (int v = 0; v < V; v++) m[v] = 0.0f;
    }
    const bool any = active && (msum > 0.0f);

    ull acc[V][2];
    #pragma unroll
    for (int v = 0; v < V; v++) { acc[v][0] = 0ull; acc[v][1] = 0ull; }

    // loader: write each element into TWO adjacent smem slots
    auto loadg = [&](int ci0, int b) {
        #pragma unroll
        for (int g = 0; g < CIPS; g++) {
            const float* __restrict__ base0 = in + (long)(ci0 + g) * CIstride;
            #pragma unroll
            for (int j = 0; j < NLOAD; j++)
                if (vm & (1u << j)) {
                    int e = tid + j * NT;
                    const float* src = base0 + goff[j];
                    cp4(&sm[b][g * SMTOT + 2 * e],     src);
                    cp4(&sm[b][g * SMTOT + 2 * e + 1], src);
                }
        }
    };

    loadg(0, 0);
    CP_COMMIT();

    for (int st = 0; st < NS; st++) {
        if (st + 1 < NS) loadg((st + 1) * CIPS, (st + 1) & 1);
        CP_COMMIT();
        CP_WAIT1();
        __syncthreads();

        if (any) {
            #pragma unroll 2
            for (int cc = 0; cc < CIPS; cc++) {
                const float* __restrict__ smb = &sm[st & 1][cc * SMTOT];
                const float* __restrict__ wci =
                    wr + (st * CIPS + cc) * (KD * KH * KW * CO) + 4 * q;
                #pragma unroll
                for (int kz = 0; kz < KD; kz++) {
                    #pragma unroll
                    for (int ky = 0; ky < KH; ky++) {
                        // duplicated row: ull slot s == (v,v) pair for element s
                        const ull* __restrict__ rowu = reinterpret_cast<const ull*>(
                            smb + ((kz * SMH) + tz * SH + ky) * SMW2) + x0 * SW;
                        ull iv2[NSEG];
                        #pragma unroll
                        for (int s = 0; s < NSEG; s++)
                            iv2[s] = rowu[s];
                        const float* __restrict__ wrow = wci + (kz * KH + ky) * KW * CO;
                        #pragma unroll
                        for (int kx = 0; kx < KW; kx++) {
                            union { float4 f; ull u[2]; } wu;
                            wu.f = *reinterpret_cast<const float4*>(wrow + kx * CO);
                            #pragma unroll
                            for (int v = 0; v < V; v++) {
                                ull iv = iv2[v * SW + kx];
                                FMA_F32X2(acc[v][0], iv, wu.u[0], acc[v][0]);
                                FMA_F32X2(acc[v][1], iv, wu.u[1], acc[v][1]);
                            }
                        }
                    }
                }
            }
        }
        __syncthreads();
    }

    if (active) {
        #pragma unroll
        for (int j = 0; j < 2; j++) {
            int ca = 4 * q + 2 * j, cb = ca + 1;
            float sca = bn[ca] * rsqrtf(bn[3 * CO + ca] + 1e-3f);
            float sha = bn[CO + ca] - bn[2 * CO + ca] * sca;
            float scb = bn[cb] * rsqrtf(bn[3 * CO + cb] + 1e-3f);
            float shb = bn[CO + cb] - bn[2 * CO + cb] * scb;
            #pragma unroll
            for (int v = 0; v < V; v++) {
                int x = x0 + v;
                if (x < OW) {
                    float a0, a1; f2_unpack(acc[v][j], a0, a1);
                    bool act = m[v] > 0.0f;
                    out[((ca * OD + z) * (long)OH + y) * OW + x] =
                        act ? fmaxf(fmaf(a0, sca, sha), 0.0f) : 0.0f;
                    out[((cb * OD + z) * (long)OH + y) * OW + x] =
                        act ? fmaxf(fmaf(a1, scb, shb), 0.0f) : 0.0f;
                }
            }
        }
    }
}

// ---------------- launch ----------------
extern "C" void kernel_launch(void* const* d_in, const int* in_sizes, int n_in,
                              void* d_out, int out_size) {
    const float* x    = (const float*)d_in[0];
    const float* mask = (const float*)d_in[1];
    WPtrs wp;
    const float* B_[12];
    for (int i = 0; i < 12; i++) {
        wp.w[i] = (const float*)d_in[2 + 2 * i];
        B_[i]   = (const float*)d_in[3 + 2 * i];
    }
    float* out = (float*)d_out;

    float *bufA, *bufB, *wr, *m2, *m3, *m4, *m5;
    int* cntp;
    cudaGetSymbolAddress((void**)&bufA, g_bufA);
    cudaGetSymbolAddress((void**)&bufB, g_bufB);
    cudaGetSymbolAddress((void**)&wr,   g_wr);
    cudaGetSymbolAddress((void**)&m2,   g_mask2);
    cudaGetSymbolAddress((void**)&m3,   g_mask3);
    cudaGetSymbolAddress((void**)&m4,   g_mask4);
    cudaGetSymbolAddress((void**)&m5,   g_mask5);
    cudaGetSymbolAddress((void**)&cntp, g_cnt);

    static const int off[12] = {0, 1728, 8640, 22464, 50112, 77760, 133056,
                                243648, 354240, 464832, 575424, 686016};

    cudaMemsetAsync(cntp, 0, sizeof(int), 0);   // DMA fill, not a kernel launch

    // kernel 0: mega-prelude
    prelude_kernel<<<(N1 + 255) / 256, 256>>>(wp, mask, wr, (float4*)bufB, m2, m3, m4, m5);

    // kernels 1,2: gather subm with tap skip
    subm_gather_kernel<4, 16><<<1024, dim3(4, 32)>>>(x, mask, wr + off[0], B_[0], bufA, D1, H1, W1);
    subm_gather_kernel<16, 16><<<1024, dim3(4, 32)>>>(bufA, mask, wr + off[1], B_[1], bufB, D1, H1, W1);

    // kernel 3: L2  <-- ncu capture lands here. CIPS=1 (dup smem 42.5KB)
    conv_smem_kernel<16, 32, 1, 4, 2, 88, 352, 3, 3, 3, 2, 2, 2, 1, 1, 1>
        <<<dim3(1, H2 / 2, D2), dim3(8, 22, 2)>>>(bufB, wr + off[2], B_[2], m2, bufA,
                                                  D1, H1, W1, D2, H2, W2);
    // L3,L4: V=8, YB=4, CIPS=1 (dup smem 25.9KB)
    conv_smem_kernel<32, 32, 1, 8, 4, 88, 352, 3, 3, 3, 1, 1, 1, 1, 1, 1>
        <<<dim3(1, H2 / 4, D2), dim3(8, 11, 4)>>>(bufA, wr + off[3], B_[3], m2, bufB,
                                                  D2, H2, W2, D2, H2, W2);
    conv_smem_kernel<32, 32, 1, 8, 4, 88, 352, 3, 3, 3, 1, 1, 1, 1, 1, 1>
        <<<dim3(1, H2 / 4, D2), dim3(8, 11, 4)>>>(bufB, wr + off[4], B_[4], m2, bufA,
                                                  D2, H2, W2, D2, H2, W2);

    // L5: CIPS=2 (dup smem 42.7KB)
    conv_smem_kernel<32, 64, 2, 4, 2, 44, 352, 3, 3, 3, 2, 2, 2, 1, 1, 1>
        <<<dim3(1, H3 / 2, D3), dim3(16, 11, 2)>>>(bufA, wr + off[5], B_[5], m3, bufB,
                                                   D2, H2, W2, D3, H3, W3);
    // L6,L7: CIPS=4 (dup smem 35.3KB)
    conv_smem_kernel<64, 64, 4, 4, 2, 44, 352, 3, 3, 3, 1, 1, 1, 1, 1, 1>
        <<<dim3(1, H3 / 2, D3), dim3(16, 11, 2)>>>(bufB, wr + off[6], B_[6], m3, bufA,
                                                   D3, H3, W3, D3, H3, W3);
    conv_smem_kernel<64, 64, 4, 4, 2, 44, 352, 3, 3, 3, 1, 1, 1, 1, 1, 1>
        <<<dim3(1, H3 / 2, D3), dim3(16, 11, 2)>>>(bufA, wr + off[7], B_[7], m3, bufB,
                                                   D3, H3, W3, D3, H3, W3);

    // L8: CIPS=4 (dup smem 25.9KB)
    conv_smem_kernel<64, 64, 4, 2, 1, 22, 176, 3, 3, 3, 2, 2, 2, 0, 1, 1>
        <<<dim3(1, H4, D4), dim3(16, 11, 1)>>>(bufB, wr + off[8], B_[8], m4, bufA,
                                               D3, H3, W3, D4, H4, W4);
    // L9,L10: CIPS=8 (dup smem 26.5KB)
    conv_smem_kernel<64, 64, 8, 2, 1, 22, 176, 3, 3, 3, 1, 1, 1, 1, 1, 1>
        <<<dim3(1, H4, D4), dim3(16, 11, 1)>>>(bufA, wr + off[9], B_[9], m4, bufB,
                                               D4, H4, W4, D4, H4, W4);
    conv_smem_kernel<64, 64, 8, 2, 1, 22, 176, 3, 3, 3, 1, 1, 1, 1, 1, 1>
        <<<dim3(1, H4, D4), dim3(16, 11, 1)>>>(bufB, wr + off[10], B_[10], m4, bufA,
                                               D4, H4, W4, D4, H4, W4);

    // L11: CIPS=16 (dup smem 33KB)
    conv_smem_kernel<64, 128, 16, 2, 1, 22, 352, 3, 1, 1, 2, 1, 1, 0, 0, 0>
        <<<dim3(1, H5, D5), dim3(32, 11, 1)>>>(bufA, wr + off[11], B_[11], m5, out,
                                               D4, H4, W4, D5, H5, W5);
}

// round 17
// speedup vs baseline: 1.2591x; 1.2591x over previous
#include <cuda_runtime.h>

typedef unsigned long long ull;

// ---------------- problem dimensions ----------------
static constexpr int D1=41, H1=200, W1=176; static constexpr int N1=D1*H1*W1;   // 1,443,200
static constexpr int D2=21, H2=100, W2=88;  static constexpr int N2=D2*H2*W2;   // 184,800
static constexpr int D3=11, H3=50,  W3=44;  static constexpr int N3=D3*H3*W3;   // 24,200
static constexpr int D4=5,  H4=25,  W4=22;  static constexpr int N4=D4*H4*W4;   // 2,750
static constexpr int D5=2,  H5=25,  W5=22;  static constexpr int N5=D5*H5*W5;   // 1,100

// ---------------- static device scratch ----------------
__device__ __align__(16) float g_bufA[16 * N1];   // 92.4 MB ping
__device__ __align__(16) float g_bufB[16 * N1];   // 92.4 MB pong
__device__ float g_mask2[N2];
__device__ float g_mask3[N3];
__device__ float g_mask4[N4];
__device__ float g_mask5[N5];
__device__ __align__(16) float g_wr[710592];      // reordered weights, all 12 layers
__device__ int   g_list[N1];
__device__ int   g_cnt;

// weight region metadata (floats)
__device__ __constant__ int c_off[12] = {0, 1728, 8640, 22464, 50112, 77760, 133056,
                                         243648, 354240, 464832, 575424, 686016};
__device__ __constant__ int c_CI[12] = {4, 16, 16, 32, 32, 32, 64, 64, 64, 64, 64, 64};
__device__ __constant__ int c_CO[12] = {16, 16, 32, 32, 32, 64, 64, 64, 64, 64, 64, 128};
__device__ __constant__ int c_K3[12] = {27, 27, 27, 27, 27, 27, 27, 27, 27, 27, 27, 3};

struct WPtrs { const float* w[12]; };

// ---------------- f32x2 + cp.async helpers ----------------
__device__ __forceinline__ ull f2_dup(float v) {
    ull r; asm("mov.b64 %0, {%1, %1};" : "=l"(r) : "f"(v)); return r;
}
__device__ __forceinline__ void f2_unpack(ull v, float& lo, float& hi) {
    asm("mov.b64 {%0, %1}, %2;" : "=f"(lo), "=f"(hi) : "l"(v));
}
#define FMA_F32X2(d, a, b, c) \
    asm("fma.rn.f32x2 %0, %1, %2, %3;" : "=l"(d) : "l"(a), "l"(b), "l"(c))

__device__ __forceinline__ void cp4(float* dst, const float* src) {
    unsigned d = (unsigned)__cvta_generic_to_shared(dst);
    asm volatile("cp.async.ca.shared.global [%0], [%1], 4;" :: "r"(d), "l"(src));
}
__device__ __forceinline__ void cp16(float* dst, const float* src) {
    unsigned d = (unsigned)__cvta_generic_to_shared(dst);
    asm volatile("cp.async.cg.shared.global [%0], [%1], 16;" :: "r"(d), "l"(src));
}
#define CP_COMMIT() asm volatile("cp.async.commit_group;" ::: "memory")
#define CP_WAIT1()  asm volatile("cp.async.wait_group 1;"  ::: "memory")

// ---------------- mask box probe (early exit) ----------------
__device__ __forceinline__ float probe_box(const float* __restrict__ mask,
                                           int z0, int z1, int y0, int y1,
                                           int x0, int x1) {
    z0 = max(z0, 0); y0 = max(y0, 0); x0 = max(x0, 0);
    z1 = min(z1, D1 - 1); y1 = min(y1, H1 - 1); x1 = min(x1, W1 - 1);
    for (int z = z0; z <= z1; z++)
        for (int y = y0; y <= y1; y++)
            for (int x = x0; x <= x1; x++)
                if (__ldg(mask + (z * H1 + y) * W1 + x) != 0.0f) return 1.0f;
    return 0.0f;
}

// ---------------- mega prelude: weights + zero bufB + compact + all masks ----------------
__global__ void prelude_kernel(WPtrs p, const float* __restrict__ mask,
                               float* __restrict__ wr, float4* __restrict__ zb,
                               float* __restrict__ m2o, float* __restrict__ m3o,
                               float* __restrict__ m4o, float* __restrict__ m5o) {
    int t  = blockIdx.x * blockDim.x + threadIdx.x;
    int nt = gridDim.x * blockDim.x;

    const int NZ4 = (16 * N1) / 4;
    for (int i = t; i < NZ4; i += nt)
        zb[i] = make_float4(0.f, 0.f, 0.f, 0.f);

    if (t < N1 && mask[t] != 0.0f) {
        int q = atomicAdd(&g_cnt, 1);
        g_list[q] = t;
    }

    if (t < 710592) {
        int L = 0, base = 0;
        #pragma unroll
        for (int i = 0; i < 12; i++) {
            int n = c_CO[i] * c_CI[i] * c_K3[i];
            if (t >= base && t < base + n) { L = i; }
            base += n;
        }
        base = c_off[L];
        int local = t - base;
        int K3 = c_K3[L], CI = c_CI[L], CO = c_CO[L];
        int k  = local % K3;
        int r  = local / K3;
        int ci = r % CI;
        int co = r / CI;
        wr[base + (ci * K3 + k) * CO + co] = p.w[L][local];
    }

    if (t < N2) {
        int x = t % W2; int r = t / W2; int y = r % H2; int z = r / H2;
        m2o[t] = probe_box(mask, 2*z-1, 2*z+1, 2*y-1, 2*y+1, 2*x-1, 2*x+1);
    }
    if (t < N3) {
        int x = t % W3; int r = t / W3; int y = r % H3; int z = r / H3;
        m3o[t] = probe_box(mask, 4*z-3, 4*z+3, 4*y-3, 4*y+3, 4*x-3, 4*x+3);
    }
    if (t < N4) {
        int x = t % W4; int r = t / W4; int y = r % H4; int z = r / H4;
        m4o[t] = probe_box(mask, 8*z-3, 8*z+11, 8*y-7, 8*y+7, 8*x-7, 8*x+7);
    }
    if (t < N5) {
        int x = t % W5; int r = t / W5; int y = r % H5; int z = r / H5;
        m5o[t] = probe_box(mask, 16*z-3, 16*z+27, 8*y-7, 8*y+7, 8*x-7, 8*x+7);
    }
}

// ---------------- sparse gather subm conv with TAP SKIP (3x3x3, s1, p1) ----------------
template<int CI, int CO>
__global__ void subm_gather_kernel(const float* __restrict__ in, const float* __restrict__ mask,
                                   const float* __restrict__ wr, const float* __restrict__ bn,
                                   float* __restrict__ out, int D, int H, int W) {
    const int q = threadIdx.x;       // [0, CO/4)
    const int n = g_cnt;
    const int DHW = D * H * W;
    for (int e = blockIdx.x * blockDim.y + threadIdx.y; e < n; e += gridDim.x * blockDim.y) {
        const int idx = g_list[e];
        const int x  = idx % W;
        const int zy = idx / W;
        const int y  = zy % H;
        const int z  = zy / H;

        float acc[4] = {0.f, 0.f, 0.f, 0.f};
        #pragma unroll
        for (int kz = 0; kz < 3; kz++) {
            int zi = z - 1 + kz; if ((unsigned)zi >= (unsigned)D) continue;
            #pragma unroll
            for (int ky = 0; ky < 3; ky++) {
                int yi = y - 1 + ky; if ((unsigned)yi >= (unsigned)H) continue;
                const int rowb = (zi * H + yi) * W + x;
                #pragma unroll
                for (int kx = 0; kx < 3; kx++) {
                    int xi = x - 1 + kx;
                    if ((unsigned)xi >= (unsigned)W) continue;
                    if (__ldg(mask + rowb + kx - 1) == 0.0f) continue;   // tap skip
                    const float* __restrict__ ptap = in + rowb + kx - 1;
                    const float* __restrict__ wtap =
                        wr + ((kz * 3 + ky) * 3 + kx) * CO + 4 * q;
                    #pragma unroll
                    for (int ci = 0; ci < CI; ci++) {
                        float iv = __ldg(ptap + ci * DHW);
                        float4 w4 = *reinterpret_cast<const float4*>(wtap + ci * 27 * CO);
                        acc[0] += iv * w4.x;
                        acc[1] += iv * w4.y;
                        acc[2] += iv * w4.z;
                        acc[3] += iv * w4.w;
                    }
                }
            }
        }
        #pragma unroll
        for (int j = 0; j < 4; j++) {
            int co = 4 * q + j;
            float g  = bn[co];
            float b  = bn[CO + co];
            float mu = bn[2 * CO + co];
            float vr = bn[3 * CO + co];
            float sc = g * rsqrtf(vr + 1e-3f);
            float sh = b - mu * sc;
            float val = fmaxf(acc[j] * sc + sh, 0.0f);
            out[((co * D + z) * (long)H + y) * W + x] = val;
        }
    }
}

// ---------------- dense conv: cp.async pipeline (16B chunked loader) + f32x2 ----------------
// CHUNK=true requires IW % 4 == 0. Compute path identical to the 1282us kernel.
template<int CI, int CO, int CIPS, int V, int YB, int OWT, int NT,
         int KD, int KH, int KW, int SD, int SH, int SW, int PD, int PH, int PW, bool CHUNK>
__global__ void __launch_bounds__(NT, 2)
conv_smem_kernel(const float* __restrict__ in, const float* __restrict__ wr,
                 const float* __restrict__ bn, const float* __restrict__ omask,
                 float* __restrict__ out,
                 int ID, int IH, int IW, int OD, int OH, int OW) {
    constexpr int NSEG   = (V - 1) * SW + KW;
    constexpr int SMH    = (YB - 1) * SH + KH;
    constexpr int SMW_E  = (OWT - 1) * SW + KW;
    constexpr int SHIFT  = CHUNK ? ((4 - (PW & 3)) & 3) : 0;
    constexpr int ODD    = SHIFT & 1;
    constexpr int OFFC   = SHIFT + PW;                       // gmem xi = u - OFFC
    constexpr int SMWP   = CHUNK ? ((SHIFT + SMW_E + 2 + 3) & ~3)
                                 : (((SMW_E + 2) + 1) & ~1);
    constexpr int SMTOT  = KD * SMH * SMWP;
    constexpr int NCHN   = CHUNK ? (KD * SMH * (SMWP / 4)) : SMTOT;
    constexpr int NLD    = (NCHN + NT - 1) / NT;
    constexpr int NS     = CI / CIPS;
    constexpr int NF2    = (NSEG - 1 + ODD) / 2 + 1;

    __shared__ __align__(16) float sm[2][CIPS * SMTOT];

    const int q   = threadIdx.x;
    const int tz  = threadIdx.z;
    const int x0  = threadIdx.y * V;
    const int y   = blockIdx.y * YB + tz;
    const int z   = blockIdx.z;
    const int tid = threadIdx.x + blockDim.x * (threadIdx.y + blockDim.y * threadIdx.z);

    const bool active = (y < OH);
    const int CIstride = ID * IH * IW;

    for (int i = tid; i < 2 * CIPS * SMTOT; i += NT)
        (&sm[0][0])[i] = 0.0f;

    // ---- precompute loader tuples (CI-invariant geometry) ----
    const int zi_base = z * SD - PD;
    const int yi_base = blockIdx.y * YB * SH - PH;
    int goff[NLD];
    unsigned msk = 0;     // CHUNK: 4 bits/chunk ; else: 1 bit/element
    #pragma unroll
    for (int j = 0; j < NLD; j++) {
        int c = tid + j * NT;
        if constexpr (CHUNK) {
            int cx  = c % (SMWP / 4);
            int row = c / (SMWP / 4);
            int r   = row % SMH;
            int kz  = row / SMH;
            int zi  = zi_base + kz;
            int yi  = yi_base + r;
            bool rv = (c < NCHN) && ((unsigned)zi < (unsigned)ID) &&
                      ((unsigned)yi < (unsigned)IH);
            goff[j] = (zi * IH + yi) * IW + 4 * cx - OFFC;
            unsigned m4 = 0;
            if (rv) {
                #pragma unroll
                for (int e = 0; e < 4; e++) {
                    int xi = 4 * cx + e - OFFC;
                    if ((unsigned)xi < (unsigned)IW) m4 |= 1u << e;
                }
            }
            msk |= m4 << (4 * j);
        } else {
            int u   = c % SMWP;
            int row = c / SMWP;
            int r   = row % SMH;
            int kz  = row / SMH;
            int zi  = zi_base + kz;
            int yi  = yi_base + r;
            int xi  = u - PW;
            bool ok = (c < NCHN) && ((unsigned)zi < (unsigned)ID) &&
                      ((unsigned)yi < (unsigned)IH) && ((unsigned)xi < (unsigned)IW);
            goff[j] = ok ? ((zi * IH + yi) * IW + xi) : 0;
            if (ok) msk |= 1u << j;
        }
    }
    __syncthreads();

    float m[V];
    float msum = 0.0f;
    if (active) {
        const int obase = (z * OH + y) * OW;
        #pragma unroll
        for (int v = 0; v < V; v++) {
            m[v] = (x0 + v < OW) ? omask[obase + x0 + v] : 0.0f;
            msum += m[v];
        }
    } else {
        #pragma unroll
        for (int v = 0; v < V; v++) m[v] = 0.0f;
    }
    const bool any = active && (msum > 0.0f);

    ull acc[V][2];
    #pragma unroll
    for (int v = 0; v < V; v++) { acc[v][0] = 0ull; acc[v][1] = 0ull; }

    auto loadg = [&](int ci0, int b) {
        #pragma unroll
        for (int g = 0; g < CIPS; g++) {
            const float* __restrict__ base0 = in + (long)(ci0 + g) * CIstride;
            #pragma unroll
            for (int j = 0; j < NLD; j++) {
                if constexpr (CHUNK) {
                    unsigned m4 = (msk >> (4 * j)) & 0xFu;
                    if (!m4) continue;
                    float* dst = &sm[b][g * SMTOT + 4 * (tid + j * NT)];
                    const float* src = base0 + goff[j];
                    if (m4 == 0xFu) {
                        cp16(dst, src);
                    } else {
                        #pragma unroll
                        for (int e = 0; e < 4; e++)
                            if ((m4 >> e) & 1u) cp4(dst + e, src + e);
                    }
                } else {
                    if ((msk >> j) & 1u)
                        cp4(&sm[b][g * SMTOT + tid + j * NT], base0 + goff[j]);
                }
            }
        }
    };

    loadg(0, 0);
    CP_COMMIT();

    for (int st = 0; st < NS; st++) {
        if (st + 1 < NS) loadg((st + 1) * CIPS, (st + 1) & 1);
        CP_COMMIT();
        CP_WAIT1();
        __syncthreads();

        if (any) {
            #pragma unroll 2
            for (int cc = 0; cc < CIPS; cc++) {
                const float* __restrict__ smb = &sm[st & 1][cc * SMTOT];
                const float* __restrict__ wci =
                    wr + (st * CIPS + cc) * (KD * KH * KW * CO) + 4 * q;
                #pragma unroll
                for (int kz = 0; kz < KD; kz++) {
                    #pragma unroll
                    for (int ky = 0; ky < KH; ky++) {
                        const float* __restrict__ rowp =
                            smb + ((kz * SMH) + tz * SH + ky) * SMWP + SHIFT - ODD + x0 * SW;
                        float2 f[NF2];
                        #pragma unroll
                        for (int k = 0; k < NF2; k++)
                            f[k] = reinterpret_cast<const float2*>(rowp)[k];
                        ull iv2[NSEG];
                        #pragma unroll
                        for (int s = 0; s < NSEG; s++) {
                            int ti = s + ODD;
                            float vv = (ti & 1) ? f[ti / 2].y : f[ti / 2].x;
                            iv2[s] = f2_dup(vv);
                        }
                        const float* __restrict__ wrow = wci + (kz * KH + ky) * KW * CO;
                        #pragma unroll
                        for (int kx = 0; kx < KW; kx++) {
                            union { float4 f4; ull u[2]; } wu;
                            wu.f4 = *reinterpret_cast<const float4*>(wrow + kx * CO);
                            #pragma unroll
                            for (int v = 0; v < V; v++) {
                                ull iv = iv2[v * SW + kx];
                                FMA_F32X2(acc[v][0], iv, wu.u[0], acc[v][0]);
                                FMA_F32X2(acc[v][1], iv, wu.u[1], acc[v][1]);
                            }
                        }
                    }
                }
            }
        }
        __syncthreads();
    }

    if (active) {
        #pragma unroll
        for (int j = 0; j < 2; j++) {
            int ca = 4 * q + 2 * j, cb = ca + 1;
            float sca = bn[ca] * rsqrtf(bn[3 * CO + ca] + 1e-3f);
            float sha = bn[CO + ca] - bn[2 * CO + ca] * sca;
            float scb = bn[cb] * rsqrtf(bn[3 * CO + cb] + 1e-3f);
            float shb = bn[CO + cb] - bn[2 * CO + cb] * scb;
            #pragma unroll
            for (int v = 0; v < V; v++) {
                int x = x0 + v;
                if (x < OW) {
                    float a0, a1; f2_unpack(acc[v][j], a0, a1);
                    bool act = m[v] > 0.0f;
                    out[((ca * OD + z) * (long)OH + y) * OW + x] =
                        act ? fmaxf(fmaf(a0, sca, sha), 0.0f) : 0.0f;
                    out[((cb * OD + z) * (long)OH + y) * OW + x] =
                        act ? fmaxf(fmaf(a1, scb, shb), 0.0f) : 0.0f;
                }
            }
        }
    }
}

// ---------------- launch ----------------
extern "C" void kernel_launch(void* const* d_in, const int* in_sizes, int n_in,
                              void* d_out, int out_size) {
    const float* x    = (const float*)d_in[0];
    const float* mask = (const float*)d_in[1];
    WPtrs wp;
    const float* B_[12];
    for (int i = 0; i < 12; i++) {
        wp.w[i] = (const float*)d_in[2 + 2 * i];
        B_[i]   = (const float*)d_in[3 + 2 * i];
    }
    float* out = (float*)d_out;

    float *bufA, *bufB, *wr, *m2, *m3, *m4, *m5;
    int* cntp;
    cudaGetSymbolAddress((void**)&bufA, g_bufA);
    cudaGetSymbolAddress((void**)&bufB, g_bufB);
    cudaGetSymbolAddress((void**)&wr,   g_wr);
    cudaGetSymbolAddress((void**)&m2,   g_mask2);
    cudaGetSymbolAddress((void**)&m3,   g_mask3);
    cudaGetSymbolAddress((void**)&m4,   g_mask4);
    cudaGetSymbolAddress((void**)&m5,   g_mask5);
    cudaGetSymbolAddress((void**)&cntp, g_cnt);

    static const int off[12] = {0, 1728, 8640, 22464, 50112, 77760, 133056,
                                243648, 354240, 464832, 575424, 686016};

    cudaMemsetAsync(cntp, 0, sizeof(int), 0);   // DMA fill, not a kernel launch

    // kernel 0: mega-prelude
    prelude_kernel<<<(N1 + 255) / 256, 256>>>(wp, mask, wr, (float4*)bufB, m2, m3, m4, m5);

    // kernels 1,2: gather subm with tap skip
    subm_gather_kernel<4, 16><<<1024, dim3(4, 32)>>>(x, mask, wr + off[0], B_[0], bufA, D1, H1, W1);
    subm_gather_kernel<16, 16><<<1024, dim3(4, 32)>>>(bufA, mask, wr + off[1], B_[1], bufB, D1, H1, W1);

    // kernel 3: L2  <-- ncu capture lands here. CHUNK loader (IW=176)
    conv_smem_kernel<16, 32, 2, 4, 2, 88, 352, 3, 3, 3, 2, 2, 2, 1, 1, 1, true>
        <<<dim3(1, H2 / 2, D2), dim3(8, 22, 2)>>>(bufB, wr + off[2], B_[2], m2, bufA,
                                                  D1, H1, W1, D2, H2, W2);
    // L3,L4: V=8, YB=4, CHUNK (IW=88)
    conv_smem_kernel<32, 32, 2, 8, 4, 88, 352, 3, 3, 3, 1, 1, 1, 1, 1, 1, true>
        <<<dim3(1, H2 / 4, D2), dim3(8, 11, 4)>>>(bufA, wr + off[3], B_[3], m2, bufB,
                                                  D2, H2, W2, D2, H2, W2);
    conv_smem_kernel<32, 32, 2, 8, 4, 88, 352, 3, 3, 3, 1, 1, 1, 1, 1, 1, true>
        <<<dim3(1, H2 / 4, D2), dim3(8, 11, 4)>>>(bufB, wr + off[4], B_[4], m2, bufA,
                                                  D2, H2, W2, D2, H2, W2);

    // L5: CIPS=4, CHUNK (IW=88)
    conv_smem_kernel<32, 64, 4, 4, 2, 44, 352, 3, 3, 3, 2, 2, 2, 1, 1, 1, true>
        <<<dim3(1, H3 / 2, D3), dim3(16, 11, 2)>>>(bufA, wr + off[5], B_[5], m3, bufB,
                                                   D2, H2, W2, D3, H3, W3);
    // L6,L7: CIPS=8, CHUNK (IW=44)
    conv_smem_kernel<64, 64, 8, 4, 2, 44, 352, 3, 3, 3, 1, 1, 1, 1, 1, 1, true>
        <<<dim3(1, H3 / 2, D3), dim3(16, 11, 2)>>>(bufB, wr + off[6], B_[6], m3, bufA,
                                                   D3, H3, W3, D3, H3, W3);
    conv_smem_kernel<64, 64, 8, 4, 2, 44, 352, 3, 3, 3, 1, 1, 1, 1, 1, 1, true>
        <<<dim3(1, H3 / 2, D3), dim3(16, 11, 2)>>>(bufA, wr + off[7], B_[7], m3, bufB,
                                                   D3, H3, W3, D3, H3, W3);

    // L8: CIPS=8, CHUNK (IW=44)
    conv_smem_kernel<64, 64, 8, 2, 1, 22, 176, 3, 3, 3, 2, 2, 2, 0, 1, 1, true>
        <<<dim3(1, H4, D4), dim3(16, 11, 1)>>>(bufB, wr + off[8], B_[8], m4, bufA,
                                               D3, H3, W3, D4, H4, W4);
    // L9,L10: elementwise loader (IW=22 not /4)
    conv_smem_kernel<64, 64, 8, 2, 1, 22, 176, 3, 3, 3, 1, 1, 1, 1, 1, 1, false>
        <<<dim3(1, H4, D4), dim3(16, 11, 1)>>>(bufA, wr + off[9], B_[9], m4, bufB,
                                               D4, H4, W4, D4, H4, W4);
    conv_smem_kernel<64, 64, 8, 2, 1, 22, 176, 3, 3, 3, 1, 1, 1, 1, 1, 1, false>
        <<<dim3(1, H4, D4), dim3(16, 11, 1)>>>(bufB, wr + off[10], B_[10], m4, bufA,
                                               D4, H4, W4, D4, H4, W4);

    // L11: elementwise loader (IW=22)
    conv_smem_kernel<64, 128, 16, 2, 1, 22, 352, 3, 1, 1, 2, 1, 1, 0, 0, 0, false>
        <<<dim3(1, H5, D5), dim3(32, 11, 1)>>>(bufA, wr + off[11], B_[11], m5, out,
                                               D4, H4, W4, D5, H5, W5);
}